// round 16
// baseline (speedup 1.0000x reference)
#include <cuda_runtime.h>
#include <cuda_fp16.h>
#include <math.h>

#define N_NODES 20000
#define DIM 128
#define KNB 16
#define STEPS 2
#define LAYERS 2
#define E_EDGES 8192
#define EDGE_WARPS_PER_BLK 8
#define EDGE_BLOCKS (E_EDGES / EDGE_WARPS_PER_BLK)   // 1024

#define PROJ_NODES_PER_WARP 2
#define PROJ_BLOCKS (N_NODES / (PROJ_NODES_PER_WARP * 8))  // 1250

#define FULL 0xffffffffu

// Scratch (static __device__ — no allocations allowed; zero-initialized)
__device__ float    g_proj[N_NODES];
__device__ float    g_self[N_NODES];
__device__ float    g_cw[LAYERS * DIM];
__device__ float    g_partials[EDGE_BLOCKS];
__device__ int      g_edge_count;
// fp16 copy of embeddings: 128 half per row = 256B/row (5.12 MB).
// Stored as uint2 per lane (4 halves); gathered as uint4 (8 halves).
__device__ uint2    g_embh[N_NODES * 32];

// ---------------------------------------------------------------------------
// K1: fused — proj[n] = emb[n]·w_n, self[n] = emb[n]·w_s, plus fp16 copy of
//     emb. 2 nodes per warp. Block 0 additionally computes
//     cw[l,d] = sum_f layer_w[l,f,d] and resets the edge counter.
// ---------------------------------------------------------------------------
__global__ void __launch_bounds__(256) proj_cw_kernel(
        const float* __restrict__ emb,
        const float* __restrict__ fc_w,
        const float* __restrict__ layer_w) {
    if (blockIdx.x == 0) {
        int t = threadIdx.x;                      // 0..255 == LAYERS*DIM
        int l = t >> 7, d = t & 127;
        const float* w = layer_w + l * DIM * DIM + d;
        float s = 0.f;
#pragma unroll 16
        for (int f = 0; f < DIM; f++) s += w[f * DIM];
        g_cw[t] = s;
        if (t == 0) g_edge_count = 0;
    }

    int warp = (blockIdx.x * blockDim.x + threadIdx.x) >> 5;
    int lane = threadIdx.x & 31;
    int n0 = warp * PROJ_NODES_PER_WARP;
    if (n0 >= N_NODES) return;

    float4 wn = reinterpret_cast<const float4*>(fc_w)[lane];
    float4 ws = reinterpret_cast<const float4*>(fc_w + DIM)[lane];

    float4 e0 = reinterpret_cast<const float4*>(emb + (size_t)(n0 + 0) * DIM)[lane];
    float4 e1 = reinterpret_cast<const float4*>(emb + (size_t)(n0 + 1) * DIM)[lane];

    // fp16 copy (coalesced 256B row stores; lane stores 4 halves = uint2)
    {
        __half2 h00 = __floats2half2_rn(e0.x, e0.y);
        __half2 h01 = __floats2half2_rn(e0.z, e0.w);
        __half2 h10 = __floats2half2_rn(e1.x, e1.y);
        __half2 h11 = __floats2half2_rn(e1.z, e1.w);
        g_embh[(size_t)(n0 + 0) * 32 + lane] =
            make_uint2(*reinterpret_cast<unsigned*>(&h00),
                       *reinterpret_cast<unsigned*>(&h01));
        g_embh[(size_t)(n0 + 1) * 32 + lane] =
            make_uint2(*reinterpret_cast<unsigned*>(&h10),
                       *reinterpret_cast<unsigned*>(&h11));
    }

    float pn0 = e0.x*wn.x + e0.y*wn.y + e0.z*wn.z + e0.w*wn.w;
    float ps0 = e0.x*ws.x + e0.y*ws.y + e0.z*ws.z + e0.w*ws.w;
    float pn1 = e1.x*wn.x + e1.y*wn.y + e1.z*wn.z + e1.w*wn.w;
    float ps1 = e1.x*ws.x + e1.y*ws.y + e1.z*ws.z + e1.w*ws.w;

#pragma unroll
    for (int off = 16; off; off >>= 1) {
        pn0 += __shfl_xor_sync(FULL, pn0, off);
        ps0 += __shfl_xor_sync(FULL, ps0, off);
        pn1 += __shfl_xor_sync(FULL, pn1, off);
        ps1 += __shfl_xor_sync(FULL, ps1, off);
    }
    if (lane == 0) {
        g_proj[n0 + 0] = pn0; g_self[n0 + 0] = ps0;
        g_proj[n0 + 1] = pn1; g_self[n0 + 1] = ps1;
    }
}

// ---------------------------------------------------------------------------
// K2: fused edge kernel, one warp per edge.
//     Heavy (label==1): both endpoints' attention rows computed in-register.
//     Gather layout: lane=(r=lane>>4, p=lane&15); lane p loads uint4 (8 fp16)
//     of row 2j+r  ->  2 rows per endpoint per iteration, 16 iterations,
//     direct HFMA2 accumulation (no conversions).
// ---------------------------------------------------------------------------
__global__ void __launch_bounds__(256) edge_kernel(
        const float* __restrict__ emb,
        const int*   __restrict__ edges,
        const int*   __restrict__ labels,
        const int*   __restrict__ neighbors,
        const float* __restrict__ fc_b,
        const float* __restrict__ layer_b,
        float* __restrict__ out) {
    __shared__ float wsum[EDGE_WARPS_PER_BLK];
    __shared__ bool  is_last;
    int warp_in_blk = threadIdx.x >> 5;
    int lane = threadIdx.x & 31;
    int e = blockIdx.x * EDGE_WARPS_PER_BLK + warp_in_blk;

    int2 ed = *reinterpret_cast<const int2*>(edges + 2 * e);
    int lab = labels[e];

    float4 se, de;
    if (lab == 1) {
        const float fcb = fc_b[0];
        // (step,k) lane view for scores: s = lane>>4, k = lane&15
        int s = lane >> 4;
        int k = lane & 15;
        int nbA = neighbors[(size_t)s * N_NODES * KNB + (size_t)ed.x * KNB + k];
        int nbB = neighbors[(size_t)s * N_NODES * KNB + (size_t)ed.y * KNB + k];

        float scA = g_proj[nbA] + g_self[ed.x] + fcb;
        float scB = g_proj[nbB] + g_self[ed.y] + fcb;
        scA = (scA >= 0.f) ? scA : 0.2f * scA;
        scB = (scB >= 0.f) ? scB : 0.2f * scB;
        float mA = scA, mB = scB;
#pragma unroll
        for (int off = 8; off; off >>= 1) {
            mA = fmaxf(mA, __shfl_xor_sync(FULL, mA, off));
            mB = fmaxf(mB, __shfl_xor_sync(FULL, mB, off));
        }
        float exA = __expf(scA - mA);
        float exB = __expf(scB - mB);
        float suA = exA, suB = exB;
#pragma unroll
        for (int off = 8; off; off >>= 1) {
            suA += __shfl_xor_sync(FULL, suA, off);
            suB += __shfl_xor_sync(FULL, suB, off);
        }
        // pre-packed half2 weights (shuffled as uint in the loop)
        __half2 hwA2 = __float2half2_rn(exA / suA);
        __half2 hwB2 = __float2half2_rn(exB / suB);
        unsigned hwAu = *reinterpret_cast<unsigned*>(&hwA2);
        unsigned hwBu = *reinterpret_cast<unsigned*>(&hwB2);

        // gather layout: r = lane>>4 (row parity), p = lane&15 (8-dim chunk)
        const int r = lane >> 4;
        const int p = lane & 15;
        const uint4* tbl = reinterpret_cast<const uint4*>(g_embh);

        __half2 aA0 = __float2half2_rn(0.f), aA1 = aA0, aA2 = aA0, aA3 = aA0;
        __half2 aB0 = aA0, aB1 = aA0, aB2 = aA0, aB3 = aA0;

#pragma unroll
        for (int j = 0; j < 16; j++) {
            int idx = 2 * j + r;
            unsigned hwa = __shfl_sync(FULL, hwAu, idx);
            int      ia  = __shfl_sync(FULL, nbA,  idx);
            unsigned hwb = __shfl_sync(FULL, hwBu, idx);
            int      ib  = __shfl_sync(FULL, nbB,  idx);
            uint4 uA = tbl[(size_t)ia * 16 + p];   // 8 halves: dims [8p,8p+8)
            uint4 uB = tbl[(size_t)ib * 16 + p];
            __half2 hA = *reinterpret_cast<__half2*>(&hwa);
            __half2 hB = *reinterpret_cast<__half2*>(&hwb);
            aA0 = __hfma2(hA, *reinterpret_cast<__half2*>(&uA.x), aA0);
            aA1 = __hfma2(hA, *reinterpret_cast<__half2*>(&uA.y), aA1);
            aA2 = __hfma2(hA, *reinterpret_cast<__half2*>(&uA.z), aA2);
            aA3 = __hfma2(hA, *reinterpret_cast<__half2*>(&uA.w), aA3);
            aB0 = __hfma2(hB, *reinterpret_cast<__half2*>(&uB.x), aB0);
            aB1 = __hfma2(hB, *reinterpret_cast<__half2*>(&uB.y), aB1);
            aB2 = __hfma2(hB, *reinterpret_cast<__half2*>(&uB.z), aB2);
            aB3 = __hfma2(hB, *reinterpret_cast<__half2*>(&uB.w), aB3);
        }

        // reduce over the two r-groups (lanes 16 apart hold rows 2j / 2j+1)
        aA0 = __hadd2(aA0, __shfl_xor_sync(FULL, aA0, 16));
        aA1 = __hadd2(aA1, __shfl_xor_sync(FULL, aA1, 16));
        aA2 = __hadd2(aA2, __shfl_xor_sync(FULL, aA2, 16));
        aA3 = __hadd2(aA3, __shfl_xor_sync(FULL, aA3, 16));
        aB0 = __hadd2(aB0, __shfl_xor_sync(FULL, aB0, 16));
        aB1 = __hadd2(aB1, __shfl_xor_sync(FULL, aB1, 16));
        aB2 = __hadd2(aB2, __shfl_xor_sync(FULL, aB2, 16));
        aB3 = __hadd2(aB3, __shfl_xor_sync(FULL, aB3, 16));

        // redistribute: lane l needs dims [4l,4l+4) = regs {2(l&1),2(l&1)+1}
        // of lane p = l>>1 (valid in both halves after the xor-16 add).
        int srcp = lane >> 1;
        __half2 tA0 = __shfl_sync(FULL, aA0, srcp);
        __half2 tA1 = __shfl_sync(FULL, aA1, srcp);
        __half2 tA2 = __shfl_sync(FULL, aA2, srcp);
        __half2 tA3 = __shfl_sync(FULL, aA3, srcp);
        __half2 tB0 = __shfl_sync(FULL, aB0, srcp);
        __half2 tB1 = __shfl_sync(FULL, aB1, srcp);
        __half2 tB2 = __shfl_sync(FULL, aB2, srcp);
        __half2 tB3 = __shfl_sync(FULL, aB3, srcp);
        bool hi = (lane & 1);
        __half2 nA0 = hi ? tA2 : tA0;
        __half2 nA1 = hi ? tA3 : tA1;
        __half2 nB0 = hi ? tB2 : tB0;
        __half2 nB1 = hi ? tB3 : tB1;

        float2 fA0 = __half22float2(nA0);
        float2 fA1 = __half22float2(nA1);
        float2 fB0 = __half22float2(nB0);
        float2 fB1 = __half22float2(nB1);

        // exact fp32 self term: 32 * emb[endpoint]
        float4 meA = reinterpret_cast<const float4*>(emb + (size_t)ed.x * DIM)[lane];
        float4 meB = reinterpret_cast<const float4*>(emb + (size_t)ed.y * DIM)[lane];
        se.x = 32.f*meA.x + fA0.x; se.y = 32.f*meA.y + fA0.y;
        se.z = 32.f*meA.z + fA1.x; se.w = 32.f*meA.w + fA1.y;
        de.x = 32.f*meB.x + fB0.x; de.y = 32.f*meB.y + fB0.y;
        de.z = 32.f*meB.z + fB1.x; de.w = 32.f*meB.w + fB1.y;
    } else {
        se = reinterpret_cast<const float4*>(emb + (size_t)ed.x * DIM)[lane];
        de = reinterpret_cast<const float4*>(emb + (size_t)ed.y * DIM)[lane];
    }

    float4 c0 = reinterpret_cast<const float4*>(g_cw)[lane];
    float4 c1 = reinterpret_cast<const float4*>(g_cw + DIM)[lane];
    float4 b0 = reinterpret_cast<const float4*>(layer_b)[lane];
    float4 b1 = reinterpret_cast<const float4*>(layer_b + DIM)[lane];

    float acc = 0.f;
    {
        float t;
        t = (fmaxf(se.x*c0.x+b0.x,0.f)+fmaxf(se.x*c1.x+b1.x,0.f)) - (fmaxf(de.x*c0.x+b0.x,0.f)+fmaxf(de.x*c1.x+b1.x,0.f)); acc += t*t;
        t = (fmaxf(se.y*c0.y+b0.y,0.f)+fmaxf(se.y*c1.y+b1.y,0.f)) - (fmaxf(de.y*c0.y+b0.y,0.f)+fmaxf(de.y*c1.y+b1.y,0.f)); acc += t*t;
        t = (fmaxf(se.z*c0.z+b0.z,0.f)+fmaxf(se.z*c1.z+b1.z,0.f)) - (fmaxf(de.z*c0.z+b0.z,0.f)+fmaxf(de.z*c1.z+b1.z,0.f)); acc += t*t;
        t = (fmaxf(se.w*c0.w+b0.w,0.f)+fmaxf(se.w*c1.w+b1.w,0.f)) - (fmaxf(de.w*c0.w+b0.w,0.f)+fmaxf(de.w*c1.w+b1.w,0.f)); acc += t*t;
    }
#pragma unroll
    for (int off = 16; off; off >>= 1)
        acc += __shfl_xor_sync(FULL, acc, off);

    if (lane == 0) {
        float diff = acc * (1.f / (float)DIM);
        float p = expf(-diff);
        float l = (float)lab - p;
        wsum[warp_in_blk] = 0.5f * l * l;
    }
    __syncthreads();
    if (threadIdx.x == 0) {
        float s = 0.f;
#pragma unroll
        for (int i = 0; i < EDGE_WARPS_PER_BLK; i++) s += wsum[i];
        g_partials[blockIdx.x] = s;
        __threadfence();
        int done = atomicAdd(&g_edge_count, 1);
        is_last = (done == EDGE_BLOCKS - 1);
    }
    __syncthreads();

    // last block: deterministic fixed-order reduction
    if (is_last) {
        __shared__ float sh[256];
        __threadfence();
        int t = threadIdx.x;
        float v = 0.f;
#pragma unroll
        for (int i = 0; i < EDGE_BLOCKS / 256; i++)
            v += g_partials[t + i * 256];
        sh[t] = v;
        __syncthreads();
#pragma unroll
        for (int stride = 128; stride; stride >>= 1) {
            if (t < stride) sh[t] += sh[t + stride];
            __syncthreads();
        }
        if (t == 0) out[0] = sh[0];
    }
}

// ---------------------------------------------------------------------------
extern "C" void kernel_launch(void* const* d_in, const int* in_sizes, int n_in,
                              void* d_out, int out_size) {
    const int*   edges     = (const int*)  d_in[0];
    const int*   labels    = (const int*)  d_in[1];
    const int*   neighbors = (const int*)  d_in[2];
    const float* emb       = (const float*)d_in[3];
    const float* fc_w      = (const float*)d_in[4];
    const float* fc_b      = (const float*)d_in[5];
    const float* layer_w   = (const float*)d_in[6];
    const float* layer_b   = (const float*)d_in[7];
    float* out = (float*)d_out;

    proj_cw_kernel<<<PROJ_BLOCKS, 256>>>(emb, fc_w, layer_w);
    edge_kernel<<<EDGE_BLOCKS, 256>>>(emb, edges, labels, neighbors,
                                      fc_b, layer_b, out);
}